// round 1
// baseline (speedup 1.0000x reference)
#include <cuda_runtime.h>

#define BB 4
#define CC 64
#define DWC 128
#define HH 256
#define WW 256
#define HWP (HH*WW)
#define EPSF 1e-6f

// ---------------- device scratch (no allocs allowed) ----------------
__device__ float g_weff1[BB][DWC][CC];
__device__ float g_weff2[BB][DWC][9];
__device__ float g_weffsca[BB][CC][CC];
__device__ float g_weff3[BB][CC][CC];
__device__ float g_weff4[BB][DWC][CC];
__device__ float g_weff5[BB][CC][CC];
__device__ float g_u[BB][DWC][HWP];      // conv1 output (128 MB)
__device__ float g_t[BB][CC][HWP];       // gated output (64 MB)
__device__ float g_poolpart[BB][CC][32]; // deterministic pool partials
__device__ float g_sca[BB][CC];

// ---------------- K0: gate + effective weights ----------------
__global__ void k0_weights(const float* __restrict__ probs,
    const float* __restrict__ w1, const float* __restrict__ la1, const float* __restrict__ lb1,
    const float* __restrict__ w2, const float* __restrict__ la2, const float* __restrict__ lb2,
    const float* __restrict__ wsca, const float* __restrict__ lasca, const float* __restrict__ lbsca,
    const float* __restrict__ w3, const float* __restrict__ la3, const float* __restrict__ lb3,
    const float* __restrict__ w4, const float* __restrict__ la4, const float* __restrict__ lb4,
    const float* __restrict__ w5, const float* __restrict__ la5, const float* __restrict__ lb5)
{
    int b = blockIdx.x;
    // top-1 gate (first max wins, matching jax top_k)
    float best = probs[b*3]; int be = 0;
    #pragma unroll
    for (int e = 1; e < 3; e++) {
        float p = probs[b*3+e];
        if (p > best) { best = p; be = e; }
    }
    float g = best * 2.0f;  // gate * SCALING
    int t = threadIdx.x;

    // conv1 (128x64, R=4) and conv4 (128x64, R=4)
    for (int idx = t; idx < DWC*CC; idx += blockDim.x) {
        int o = idx >> 6, i = idx & 63;
        float s1 = 0.f, s4 = 0.f;
        #pragma unroll
        for (int r = 0; r < 4; r++) {
            s1 += lb1[(be*DWC+o)*4+r] * la1[(be*4+r)*CC+i];
            s4 += lb4[(be*DWC+o)*4+r] * la4[(be*4+r)*CC+i];
        }
        g_weff1[b][o][i] = w1[idx] + g*s1;
        g_weff4[b][o][i] = w4[idx] + g*s4;
    }
    // conv2 depthwise: dw = (lb2(384,12) @ la2(12,3)).reshape(128,1,3,3)
    for (int idx = t; idx < DWC*9; idx += blockDim.x) {
        int row = idx / 3, col = idx % 3;  // flat idx == row*3+col == o*9+kh*3+kw
        float s = 0.f;
        #pragma unroll
        for (int r = 0; r < 12; r++)
            s += lb2[(be*384+row)*12+r] * la2[(be*12+r)*3+col];
        g_weff2[b][idx/9][idx%9] = w2[idx] + g*s;
    }
    // sca / conv3 / conv5 (all 64x64, R=4)
    for (int idx = t; idx < CC*CC; idx += blockDim.x) {
        int o = idx >> 6, i = idx & 63;
        float s1 = 0.f, s2 = 0.f, s3 = 0.f;
        #pragma unroll
        for (int r = 0; r < 4; r++) {
            s1 += lbsca[(be*CC+o)*4+r] * lasca[(be*4+r)*CC+i];
            s2 += lb3 [(be*CC+o)*4+r] * la3 [(be*4+r)*CC+i];
            s3 += lb5 [(be*CC+o)*4+r] * la5 [(be*4+r)*CC+i];
        }
        g_weffsca[b][o][i] = wsca[idx] + g*s1;
        g_weff3 [b][o][i] = w3 [idx] + g*s2;
        g_weff5 [b][o][i] = w5 [idx] + g*s3;
    }
}

// ---------------- K1: LN1 + conv1 (64 -> 128), 128-pixel tiles ----------------
#define TP1 128
#define XS1 (TP1+4)   // 132 floats row stride (16B aligned, conflict-staggered)
#define WS1 (DWC+4)   // 132

__global__ __launch_bounds__(256) void k1_ln_conv1(
    const float* __restrict__ inp, const float* __restrict__ ln1w,
    const float* __restrict__ ln1b, const float* __restrict__ b1)
{
    extern __shared__ float sm[];
    float* xs   = sm;               // 64*132
    float* ws   = xs + 64*XS1;      // 64*132
    float* psum = ws + 64*WS1;      // 2*128
    float* psq  = psum + 2*TP1;     // 2*128
    float* mu   = psq + 2*TP1;      // 128
    float* rstd = mu + TP1;         // 128

    int b = blockIdx.y;
    int pixbase = blockIdx.x * TP1;
    int t = threadIdx.x;
    const float* X = inp + (size_t)b*CC*HWP + pixbase;

    int pix = t & (TP1-1);
    int crow = t >> 7;  // 0 or 1 -> even/odd channels
    float s = 0.f, sq = 0.f;
    #pragma unroll
    for (int i = 0; i < 32; i++) {
        int c = crow + 2*i;
        float v = X[(size_t)c*HWP + pix];
        xs[c*XS1 + pix] = v; s += v; sq += v*v;
    }
    psum[crow*TP1+pix] = s; psq[crow*TP1+pix] = sq;
    __syncthreads();
    if (t < TP1) {
        float m = (psum[t]+psum[TP1+t]) * (1.f/CC);
        float var = (psq[t]+psq[TP1+t]) * (1.f/CC) - m*m;
        mu[t] = m; rstd[t] = rsqrtf(var + EPSF);
    }
    // stage weights transposed: ws[k][oc]
    for (int idx = t; idx < DWC*CC; idx += 256) {
        int oc = idx >> 6, k = idx & 63;
        ws[k*WS1 + oc] = g_weff1[b][oc][k];
    }
    __syncthreads();
    #pragma unroll
    for (int i = 0; i < 32; i++) {
        int c = crow + 2*i;
        xs[c*XS1+pix] = (xs[c*XS1+pix]-mu[pix])*rstd[pix]*ln1w[c] + ln1b[c];
    }
    __syncthreads();

    // GEMM: 8 oc x 8 pix per thread; 64 FMA per 6 shared loads
    int oc0 = (t >> 4) * 8;
    int p0  = (t & 15) * 8;
    float acc[8][8];
    #pragma unroll
    for (int o = 0; o < 8; o++)
        #pragma unroll
        for (int p = 0; p < 8; p++) acc[o][p] = 0.f;

    #pragma unroll 4
    for (int k = 0; k < CC; k++) {
        const float* xr = xs + k*XS1 + p0;
        float4 xa = *(const float4*)xr;
        float4 xb = *(const float4*)(xr+4);
        const float* wr = ws + k*WS1 + oc0;
        float4 wa = *(const float4*)wr;
        float4 wb = *(const float4*)(wr+4);
        float xv[8] = {xa.x,xa.y,xa.z,xa.w,xb.x,xb.y,xb.z,xb.w};
        float wv[8] = {wa.x,wa.y,wa.z,wa.w,wb.x,wb.y,wb.z,wb.w};
        #pragma unroll
        for (int o = 0; o < 8; o++)
            #pragma unroll
            for (int p = 0; p < 8; p++)
                acc[o][p] = fmaf(wv[o], xv[p], acc[o][p]);
    }
    #pragma unroll
    for (int o = 0; o < 8; o++) {
        int oc = oc0 + o;
        float bias = b1[oc];
        float* U = &g_u[b][oc][pixbase + p0];
        float4 v0 = {acc[o][0]+bias, acc[o][1]+bias, acc[o][2]+bias, acc[o][3]+bias};
        float4 v1 = {acc[o][4]+bias, acc[o][5]+bias, acc[o][6]+bias, acc[o][7]+bias};
        *(float4*)U = v0; *(float4*)(U+4) = v1;
    }
}

// ---------------- K2: depthwise 3x3 + SimpleGate + pool partials ----------------
__global__ __launch_bounds__(256) void k2_dw_gate_pool(const float* __restrict__ b2)
{
    __shared__ float u0[10*258];
    __shared__ float u1[10*258];
    __shared__ float redbuf[8];
    int b = blockIdx.z, j = blockIdx.y;
    int r0 = blockIdx.x * 8;
    int t = threadIdx.x;
    const float* U0 = g_u[b][j];
    const float* U1 = g_u[b][j+CC];
    for (int idx = t; idx < 10*256; idx += 256) {
        int rr = idx >> 8, col = idx & 255;
        int row = r0 - 1 + rr;
        float v0 = 0.f, v1 = 0.f;
        if (row >= 0 && row < HH) { v0 = U0[row*WW+col]; v1 = U1[row*WW+col]; }
        u0[rr*258+col+1] = v0; u1[rr*258+col+1] = v1;
    }
    if (t < 10) { u0[t*258] = 0.f; u0[t*258+257] = 0.f; u1[t*258] = 0.f; u1[t*258+257] = 0.f; }
    float wa[9], wb[9];
    #pragma unroll
    for (int i = 0; i < 9; i++) { wa[i] = g_weff2[b][j][i]; wb[i] = g_weff2[b][j+CC][i]; }
    float biasA = b2[j], biasB = b2[j+CC];
    __syncthreads();

    float lsum = 0.f;
    #pragma unroll
    for (int i = 0; i < 8; i++) {
        float a = biasA, c = biasB;
        #pragma unroll
        for (int kh = 0; kh < 3; kh++)
            #pragma unroll
            for (int kw = 0; kw < 3; kw++) {
                a = fmaf(wa[kh*3+kw], u0[(i+kh)*258 + t + kw], a);
                c = fmaf(wb[kh*3+kw], u1[(i+kh)*258 + t + kw], c);
            }
        float prod = a * c;
        g_t[b][j][(r0+i)*WW + t] = prod;
        lsum += prod;
    }
    #pragma unroll
    for (int off = 16; off > 0; off >>= 1) lsum += __shfl_down_sync(0xffffffffu, lsum, off);
    if ((t & 31) == 0) redbuf[t >> 5] = lsum;
    __syncthreads();
    if (t == 0) {
        float tot = 0.f;
        #pragma unroll
        for (int i = 0; i < 8; i++) tot += redbuf[i];
        g_poolpart[b][j][blockIdx.x] = tot;   // deterministic (no atomics)
    }
}

// ---------------- K3: SCA 1x1 conv on pooled ----------------
__global__ void k3_sca(const float* __restrict__ bsca)
{
    __shared__ float pl[CC];
    int b = blockIdx.x, o = threadIdx.x;
    float s = 0.f;
    #pragma unroll
    for (int p = 0; p < 32; p++) s += g_poolpart[b][o][p];
    pl[o] = s;
    __syncthreads();
    float acc = 0.f;
    #pragma unroll 8
    for (int i = 0; i < CC; i++) acc += g_weffsca[b][o][i] * pl[i];
    g_sca[b][o] = bsca[o] + acc * (1.f/HWP);
}

// ---------------- K4: x*sca -> conv3 -> residual -> LN2 -> conv4 -> gate -> conv5 -> out ----------------
#define TP4 64
#define S4 (TP4+4)   // 68
#define W4S (DWC+4)  // 132

__global__ __launch_bounds__(256) void k4_final(
    const float* __restrict__ inp, const float* __restrict__ ln2w, const float* __restrict__ ln2b,
    const float* __restrict__ b3, const float* __restrict__ b4, const float* __restrict__ b5,
    const float* __restrict__ beta, const float* __restrict__ gamma,
    float* __restrict__ out)
{
    extern __shared__ float sm[];
    float* bufA = sm;               // 64*68 (x / normalized / gate, reused)
    float* bufB = bufA + CC*S4;     // 64*68 (y)
    float* w3s  = bufB + CC*S4;     // 64*68
    float* w5s  = w3s + CC*S4;      // 64*68
    float* w4s  = w5s + CC*S4;      // 64*132
    float* mu   = w4s + CC*W4S;     // 64
    float* rstd = mu + TP4;         // 64
    float* redS = rstd + TP4;       // 4*64
    float* redQ = redS + 4*TP4;     // 4*64
    float* scas = redQ + 4*TP4;     // 64

    int b = blockIdx.y;
    int pixbase = blockIdx.x * TP4;
    int t = threadIdx.x;

    for (int idx = t; idx < CC*CC; idx += 256) {
        int oc = idx >> 6, k = idx & 63;
        w3s[k*S4+oc] = g_weff3[b][oc][k];
        w5s[k*S4+oc] = g_weff5[b][oc][k];
    }
    for (int idx = t; idx < DWC*CC; idx += 256) {
        int oc = idx >> 6, k = idx & 63;
        w4s[k*W4S+oc] = g_weff4[b][oc][k];
    }
    if (t < CC) scas[t] = g_sca[b][t];
    __syncthreads();

    // bufA = t * sca
    for (int idx = t; idx < CC*TP4; idx += 256) {
        int c = idx >> 6, pix = idx & 63;
        bufA[c*S4+pix] = g_t[b][c][pixbase+pix] * scas[c];
    }
    __syncthreads();

    int g4 = t >> 4, p16 = t & 15;
    int p0 = p16 * 4;

    // conv3 (64->64): 4 oc x 4 pix per thread, then y = inp + (.+b3)*beta -> bufB
    {
        int oc0 = g4 * 4;
        float acc[4][4];
        #pragma unroll
        for (int o = 0; o < 4; o++)
            #pragma unroll
            for (int p = 0; p < 4; p++) acc[o][p] = 0.f;
        #pragma unroll 4
        for (int k = 0; k < CC; k++) {
            float4 xv = *(const float4*)(bufA + k*S4 + p0);
            float4 wv = *(const float4*)(w3s + k*S4 + oc0);
            float X[4] = {xv.x,xv.y,xv.z,xv.w}, W[4] = {wv.x,wv.y,wv.z,wv.w};
            #pragma unroll
            for (int o = 0; o < 4; o++)
                #pragma unroll
                for (int p = 0; p < 4; p++) acc[o][p] = fmaf(W[o], X[p], acc[o][p]);
        }
        #pragma unroll
        for (int o = 0; o < 4; o++) {
            int oc = oc0 + o;
            const float* IP = inp + ((size_t)(b*CC+oc))*HWP + pixbase + p0;
            float4 iv = *(const float4*)IP;
            float bb = b3[oc], bt = beta[oc];
            bufB[oc*S4+p0+0] = iv.x + (acc[o][0]+bb)*bt;
            bufB[oc*S4+p0+1] = iv.y + (acc[o][1]+bb)*bt;
            bufB[oc*S4+p0+2] = iv.z + (acc[o][2]+bb)*bt;
            bufB[oc*S4+p0+3] = iv.w + (acc[o][3]+bb)*bt;
        }
    }
    __syncthreads();

    // LN2 stats over y
    {
        int p = t >> 2, q = t & 3;
        float s = 0.f, sq = 0.f;
        #pragma unroll
        for (int c = 0; c < 16; c++) {
            float v = bufB[(q*16+c)*S4 + p];
            s += v; sq += v*v;
        }
        redS[q*TP4+p] = s; redQ[q*TP4+p] = sq;
    }
    __syncthreads();
    if (t < TP4) {
        float s  = redS[t]+redS[TP4+t]+redS[2*TP4+t]+redS[3*TP4+t];
        float sq = redQ[t]+redQ[TP4+t]+redQ[2*TP4+t]+redQ[3*TP4+t];
        float m = s * (1.f/CC);
        float var = sq * (1.f/CC) - m*m;
        mu[t] = m; rstd[t] = rsqrtf(var + EPSF);
    }
    __syncthreads();
    for (int idx = t; idx < CC*TP4; idx += 256) {
        int c = idx >> 6, pix = idx & 63;
        bufA[c*S4+pix] = (bufB[c*S4+pix]-mu[pix])*rstd[pix]*ln2w[c] + ln2b[c];
    }
    __syncthreads();

    // conv4 (64->128): 8 oc x 4 pix per thread
    float acc4[8][4];
    int oc4 = g4 * 8;
    #pragma unroll
    for (int o = 0; o < 8; o++)
        #pragma unroll
        for (int p = 0; p < 4; p++) acc4[o][p] = 0.f;
    #pragma unroll 4
    for (int k = 0; k < CC; k++) {
        float4 xv  = *(const float4*)(bufA + k*S4 + p0);
        float4 wv0 = *(const float4*)(w4s + k*W4S + oc4);
        float4 wv1 = *(const float4*)(w4s + k*W4S + oc4 + 4);
        float X[4] = {xv.x,xv.y,xv.z,xv.w};
        float W[8] = {wv0.x,wv0.y,wv0.z,wv0.w,wv1.x,wv1.y,wv1.z,wv1.w};
        #pragma unroll
        for (int o = 0; o < 8; o++)
            #pragma unroll
            for (int p = 0; p < 4; p++) acc4[o][p] = fmaf(W[o], X[p], acc4[o][p]);
    }
    __syncthreads();
    // SimpleGate: upper half to bufA, then lower half multiplies in place
    if (oc4 >= CC) {
        #pragma unroll
        for (int o = 0; o < 8; o++) {
            float bb = b4[oc4+o];
            #pragma unroll
            for (int p = 0; p < 4; p++) bufA[(oc4-CC+o)*S4+p0+p] = acc4[o][p] + bb;
        }
    }
    __syncthreads();
    if (oc4 < CC) {
        #pragma unroll
        for (int o = 0; o < 8; o++) {
            float bb = b4[oc4+o];
            #pragma unroll
            for (int p = 0; p < 4; p++) {
                float upper = bufA[(oc4+o)*S4+p0+p];
                bufA[(oc4+o)*S4+p0+p] = (acc4[o][p] + bb) * upper;
            }
        }
    }
    __syncthreads();

    // conv5 (64->64) + final residual
    {
        int oc0 = g4 * 4;
        float acc[4][4];
        #pragma unroll
        for (int o = 0; o < 4; o++)
            #pragma unroll
            for (int p = 0; p < 4; p++) acc[o][p] = 0.f;
        #pragma unroll 4
        for (int k = 0; k < CC; k++) {
            float4 xv = *(const float4*)(bufA + k*S4 + p0);
            float4 wv = *(const float4*)(w5s + k*S4 + oc0);
            float X[4] = {xv.x,xv.y,xv.z,xv.w}, W[4] = {wv.x,wv.y,wv.z,wv.w};
            #pragma unroll
            for (int o = 0; o < 4; o++)
                #pragma unroll
                for (int p = 0; p < 4; p++) acc[o][p] = fmaf(W[o], X[p], acc[o][p]);
        }
        #pragma unroll
        for (int o = 0; o < 4; o++) {
            int oc = oc0 + o;
            float bb = b5[oc], gm = gamma[oc];
            float* OP = out + ((size_t)(b*CC+oc))*HWP + pixbase + p0;
            float4 ov;
            ov.x = bufB[oc*S4+p0+0] + (acc[o][0]+bb)*gm;
            ov.y = bufB[oc*S4+p0+1] + (acc[o][1]+bb)*gm;
            ov.z = bufB[oc*S4+p0+2] + (acc[o][2]+bb)*gm;
            ov.w = bufB[oc*S4+p0+3] + (acc[o][3]+bb)*gm;
            *(float4*)OP = ov;
        }
    }
}

// ---------------- launch ----------------
extern "C" void kernel_launch(void* const* d_in, const int* in_sizes, int n_in,
                              void* d_out, int out_size)
{
    const float* inp   = (const float*)d_in[0];
    const float* probs = (const float*)d_in[1];
    const float* ln1w  = (const float*)d_in[2];
    const float* ln1b  = (const float*)d_in[3];
    const float* ln2w  = (const float*)d_in[4];
    const float* ln2b  = (const float*)d_in[5];
    const float* w1    = (const float*)d_in[6];
    const float* b1    = (const float*)d_in[7];
    const float* la1   = (const float*)d_in[8];
    const float* lb1   = (const float*)d_in[9];
    const float* w2    = (const float*)d_in[10];
    const float* b2    = (const float*)d_in[11];
    const float* la2   = (const float*)d_in[12];
    const float* lb2   = (const float*)d_in[13];
    const float* wsca  = (const float*)d_in[14];
    const float* bsca  = (const float*)d_in[15];
    const float* la_s  = (const float*)d_in[16];
    const float* lb_s  = (const float*)d_in[17];
    const float* w3    = (const float*)d_in[18];
    const float* b3    = (const float*)d_in[19];
    const float* la3   = (const float*)d_in[20];
    const float* lb3   = (const float*)d_in[21];
    const float* w4    = (const float*)d_in[22];
    const float* b4    = (const float*)d_in[23];
    const float* la4   = (const float*)d_in[24];
    const float* lb4   = (const float*)d_in[25];
    const float* w5    = (const float*)d_in[26];
    const float* b5    = (const float*)d_in[27];
    const float* la5   = (const float*)d_in[28];
    const float* lb5   = (const float*)d_in[29];
    const float* beta  = (const float*)d_in[30];
    const float* gamma = (const float*)d_in[31];
    float* out = (float*)d_out;

    const int smem1 = (64*XS1 + 64*WS1 + 2*TP1 + 2*TP1 + TP1 + TP1) * (int)sizeof(float);
    const int smem4 = (CC*S4*4 + CC*W4S + TP4*2 + 4*TP4*2 + CC) * (int)sizeof(float);
    cudaFuncSetAttribute(k1_ln_conv1, cudaFuncAttributeMaxDynamicSharedMemorySize, smem1);
    cudaFuncSetAttribute(k4_final,    cudaFuncAttributeMaxDynamicSharedMemorySize, smem4);

    k0_weights<<<BB, 256>>>(probs, w1, la1, lb1, w2, la2, lb2,
                            wsca, la_s, lb_s, w3, la3, lb3,
                            w4, la4, lb4, w5, la5, lb5);
    k1_ln_conv1<<<dim3(HWP/TP1, BB), 256, smem1>>>(inp, ln1w, ln1b, b1);
    k2_dw_gate_pool<<<dim3(HH/8, CC, BB), 256>>>(b2);
    k3_sca<<<BB, CC>>>(bsca);
    k4_final<<<dim3(HWP/TP4, BB), 256, smem4>>>(inp, ln2w, ln2b, b3, b4, b5,
                                                beta, gamma, out);
}

// round 2
// speedup vs baseline: 1.0512x; 1.0512x over previous
#include <cuda_runtime.h>

#define BB 4
#define CC 64
#define DWC 128
#define HH 256
#define WW 256
#define HWP (HH*WW)
#define EPSF 1e-6f

// packed f32x2 helpers (ptxas never emits FFMA2 from C++ — must use PTX)
#define PACK2(d, s)   asm("mov.b64 %0, {%1, %1};" : "=l"(d) : "f"(s))
#define FMA2(c, a, b) asm("fma.rn.f32x2 %0, %1, %2, %0;" : "+l"(c) : "l"(a), "l"(b))
#define ADD2(d, a, b) asm("add.rn.f32x2 %0, %1, %2;" : "=l"(d) : "l"(a), "l"(b))
#define UNPACK2(lo, hi, v) asm("mov.b64 {%0, %1}, %2;" : "=f"(lo), "=f"(hi) : "l"(v))

typedef unsigned long long u64;

// ---------------- device scratch (no allocs allowed) ----------------
__device__ float g_weff1[BB][DWC][CC];
__device__ float g_weff2[BB][DWC][9];
__device__ float g_weffsca[BB][CC][CC];
__device__ float g_weff3[BB][CC][CC];
__device__ float g_weff4[BB][DWC][CC];
__device__ float g_weff5[BB][CC][CC];
__device__ float g_u[BB][DWC][HWP];      // conv1 output (128 MB)
__device__ float g_t[BB][CC][HWP];       // gated output (64 MB)
__device__ float g_poolpart[BB][CC][32]; // deterministic pool partials
__device__ float g_sca[BB][CC];

// ---------------- K0: gate + effective weights ----------------
__global__ void k0_weights(const float* __restrict__ probs,
    const float* __restrict__ w1, const float* __restrict__ la1, const float* __restrict__ lb1,
    const float* __restrict__ w2, const float* __restrict__ la2, const float* __restrict__ lb2,
    const float* __restrict__ wsca, const float* __restrict__ lasca, const float* __restrict__ lbsca,
    const float* __restrict__ w3, const float* __restrict__ la3, const float* __restrict__ lb3,
    const float* __restrict__ w4, const float* __restrict__ la4, const float* __restrict__ lb4,
    const float* __restrict__ w5, const float* __restrict__ la5, const float* __restrict__ lb5)
{
    int b = blockIdx.x;
    float best = probs[b*3]; int be = 0;
    #pragma unroll
    for (int e = 1; e < 3; e++) {
        float p = probs[b*3+e];
        if (p > best) { best = p; be = e; }
    }
    float g = best * 2.0f;  // gate * SCALING
    int t = threadIdx.x;

    for (int idx = t; idx < DWC*CC; idx += blockDim.x) {
        int o = idx >> 6, i = idx & 63;
        float s1 = 0.f, s4 = 0.f;
        #pragma unroll
        for (int r = 0; r < 4; r++) {
            s1 += lb1[(be*DWC+o)*4+r] * la1[(be*4+r)*CC+i];
            s4 += lb4[(be*DWC+o)*4+r] * la4[(be*4+r)*CC+i];
        }
        g_weff1[b][o][i] = w1[idx] + g*s1;
        g_weff4[b][o][i] = w4[idx] + g*s4;
    }
    for (int idx = t; idx < DWC*9; idx += blockDim.x) {
        int row = idx / 3, col = idx % 3;
        float s = 0.f;
        #pragma unroll
        for (int r = 0; r < 12; r++)
            s += lb2[(be*384+row)*12+r] * la2[(be*12+r)*3+col];
        g_weff2[b][idx/9][idx%9] = w2[idx] + g*s;
    }
    for (int idx = t; idx < CC*CC; idx += blockDim.x) {
        int o = idx >> 6, i = idx & 63;
        float s1 = 0.f, s2 = 0.f, s3 = 0.f;
        #pragma unroll
        for (int r = 0; r < 4; r++) {
            s1 += lbsca[(be*CC+o)*4+r] * lasca[(be*4+r)*CC+i];
            s2 += lb3 [(be*CC+o)*4+r] * la3 [(be*4+r)*CC+i];
            s3 += lb5 [(be*CC+o)*4+r] * la5 [(be*4+r)*CC+i];
        }
        g_weffsca[b][o][i] = wsca[idx] + g*s1;
        g_weff3 [b][o][i] = w3 [idx] + g*s2;
        g_weff5 [b][o][i] = w5 [idx] + g*s3;
    }
}

// ---------------- K1: LN1 + conv1 (64 -> 128), 128-pixel tiles, FFMA2 ----------------
#define TP1 128
#define XS1 (TP1+4)   // 132
#define WS1 (DWC+4)   // 132

__global__ __launch_bounds__(256) void k1_ln_conv1(
    const float* __restrict__ inp, const float* __restrict__ ln1w,
    const float* __restrict__ ln1b, const float* __restrict__ b1)
{
    extern __shared__ float sm[];
    float* xs   = sm;               // 64*132
    float* ws   = xs + 64*XS1;      // 64*132
    float* psum = ws + 64*WS1;      // 2*128
    float* psq  = psum + 2*TP1;     // 2*128
    float* mu   = psq + 2*TP1;      // 128
    float* rstd = mu + TP1;         // 128

    int b = blockIdx.y;
    int pixbase = blockIdx.x * TP1;
    int t = threadIdx.x;
    const float* X = inp + (size_t)b*CC*HWP + pixbase;

    int pix = t & (TP1-1);
    int crow = t >> 7;
    float s = 0.f, sq = 0.f;
    #pragma unroll
    for (int i = 0; i < 32; i++) {
        int c = crow + 2*i;
        float v = X[(size_t)c*HWP + pix];
        xs[c*XS1 + pix] = v; s += v; sq += v*v;
    }
    psum[crow*TP1+pix] = s; psq[crow*TP1+pix] = sq;
    __syncthreads();
    if (t < TP1) {
        float m = (psum[t]+psum[TP1+t]) * (1.f/CC);
        float var = (psq[t]+psq[TP1+t]) * (1.f/CC) - m*m;
        mu[t] = m; rstd[t] = rsqrtf(var + EPSF);
    }
    for (int idx = t; idx < DWC*CC; idx += 256) {
        int oc = idx >> 6, k = idx & 63;
        ws[k*WS1 + oc] = g_weff1[b][oc][k];
    }
    __syncthreads();
    #pragma unroll
    for (int i = 0; i < 32; i++) {
        int c = crow + 2*i;
        xs[c*XS1+pix] = (xs[c*XS1+pix]-mu[pix])*rstd[pix]*ln1w[c] + ln1b[c];
    }
    __syncthreads();

    // GEMM: 8 oc x 8 pix (= 4 pixel-pairs) per thread, FFMA2 mainloop
    int oc0 = (t >> 4) * 8;
    int p0  = (t & 15) * 8;
    u64 acc[8][4];
    #pragma unroll
    for (int o = 0; o < 8; o++)
        #pragma unroll
        for (int p = 0; p < 4; p++) acc[o][p] = 0ULL;

    #pragma unroll 2
    for (int k = 0; k < CC; k++) {
        const u64* xr = (const u64*)(xs + k*XS1 + p0);
        ulonglong2 xa = *(const ulonglong2*)xr;
        ulonglong2 xb = *(const ulonglong2*)(xr+2);
        u64 xv[4] = {xa.x, xa.y, xb.x, xb.y};
        const float* wr = ws + k*WS1 + oc0;
        float4 w0 = *(const float4*)wr;
        float4 w1v = *(const float4*)(wr+4);
        float wsc[8] = {w0.x,w0.y,w0.z,w0.w,w1v.x,w1v.y,w1v.z,w1v.w};
        u64 wp[8];
        #pragma unroll
        for (int o = 0; o < 8; o++) PACK2(wp[o], wsc[o]);
        #pragma unroll
        for (int o = 0; o < 8; o++)
            #pragma unroll
            for (int p = 0; p < 4; p++)
                FMA2(acc[o][p], wp[o], xv[p]);
    }
    #pragma unroll
    for (int o = 0; o < 8; o++) {
        int oc = oc0 + o;
        u64 bp; PACK2(bp, b1[oc]);
        #pragma unroll
        for (int p = 0; p < 4; p++) ADD2(acc[o][p], acc[o][p], bp);
        u64* U = (u64*)&g_u[b][oc][pixbase + p0];
        *(ulonglong2*)U     = make_ulonglong2(acc[o][0], acc[o][1]);
        *(ulonglong2*)(U+2) = make_ulonglong2(acc[o][2], acc[o][3]);
    }
}

// ---------------- K2: depthwise 3x3 + SimpleGate + pool partials ----------------
__global__ __launch_bounds__(256) void k2_dw_gate_pool(const float* __restrict__ b2)
{
    __shared__ float u0[10*258];
    __shared__ float u1[10*258];
    __shared__ float redbuf[8];
    int b = blockIdx.z, j = blockIdx.y;
    int r0 = blockIdx.x * 8;
    int t = threadIdx.x;
    const float* U0 = g_u[b][j];
    const float* U1 = g_u[b][j+CC];
    for (int idx = t; idx < 10*256; idx += 256) {
        int rr = idx >> 8, col = idx & 255;
        int row = r0 - 1 + rr;
        float v0 = 0.f, v1 = 0.f;
        if (row >= 0 && row < HH) { v0 = U0[row*WW+col]; v1 = U1[row*WW+col]; }
        u0[rr*258+col+1] = v0; u1[rr*258+col+1] = v1;
    }
    if (t < 10) { u0[t*258] = 0.f; u0[t*258+257] = 0.f; u1[t*258] = 0.f; u1[t*258+257] = 0.f; }
    float wa[9], wb[9];
    #pragma unroll
    for (int i = 0; i < 9; i++) { wa[i] = g_weff2[b][j][i]; wb[i] = g_weff2[b][j+CC][i]; }
    float biasA = b2[j], biasB = b2[j+CC];
    __syncthreads();

    float lsum = 0.f;
    #pragma unroll
    for (int i = 0; i < 8; i++) {
        float a = biasA, c = biasB;
        #pragma unroll
        for (int kh = 0; kh < 3; kh++)
            #pragma unroll
            for (int kw = 0; kw < 3; kw++) {
                a = fmaf(wa[kh*3+kw], u0[(i+kh)*258 + t + kw], a);
                c = fmaf(wb[kh*3+kw], u1[(i+kh)*258 + t + kw], c);
            }
        float prod = a * c;
        g_t[b][j][(r0+i)*WW + t] = prod;
        lsum += prod;
    }
    #pragma unroll
    for (int off = 16; off > 0; off >>= 1) lsum += __shfl_down_sync(0xffffffffu, lsum, off);
    if ((t & 31) == 0) redbuf[t >> 5] = lsum;
    __syncthreads();
    if (t == 0) {
        float tot = 0.f;
        #pragma unroll
        for (int i = 0; i < 8; i++) tot += redbuf[i];
        g_poolpart[b][j][blockIdx.x] = tot;
    }
}

// ---------------- K3: SCA 1x1 conv on pooled ----------------
__global__ void k3_sca(const float* __restrict__ bsca)
{
    __shared__ float pl[CC];
    int b = blockIdx.x, o = threadIdx.x;
    float s = 0.f;
    #pragma unroll
    for (int p = 0; p < 32; p++) s += g_poolpart[b][o][p];
    pl[o] = s;
    __syncthreads();
    float acc = 0.f;
    #pragma unroll 8
    for (int i = 0; i < CC; i++) acc += g_weffsca[b][o][i] * pl[i];
    g_sca[b][o] = bsca[o] + acc * (1.f/HWP);
}

// ---------------- K4: fused tail, FFMA2 oc-pair packing ----------------
#define TP4 64
#define S4 (TP4+4)   // 68
#define W4S (DWC+4)  // 132

__global__ __launch_bounds__(256) void k4_final(
    const float* __restrict__ inp, const float* __restrict__ ln2w, const float* __restrict__ ln2b,
    const float* __restrict__ b3, const float* __restrict__ b4, const float* __restrict__ b5,
    const float* __restrict__ beta, const float* __restrict__ gamma,
    float* __restrict__ out)
{
    extern __shared__ float sm[];
    float* bufA = sm;               // 64*68
    float* bufB = bufA + CC*S4;     // 64*68
    float* w3s  = bufB + CC*S4;     // 64*68
    float* w5s  = w3s + CC*S4;      // 64*68
    float* w4s  = w5s + CC*S4;      // 64*132
    float* mu   = w4s + CC*W4S;     // 64
    float* rstd = mu + TP4;         // 64
    float* redS = rstd + TP4;       // 4*64
    float* redQ = redS + 4*TP4;     // 4*64
    float* scas = redQ + 4*TP4;     // 64

    int b = blockIdx.y;
    int pixbase = blockIdx.x * TP4;
    int t = threadIdx.x;

    for (int idx = t; idx < CC*CC; idx += 256) {
        int oc = idx >> 6, k = idx & 63;
        w3s[k*S4+oc] = g_weff3[b][oc][k];
        w5s[k*S4+oc] = g_weff5[b][oc][k];
    }
    for (int idx = t; idx < DWC*CC; idx += 256) {
        int oc = idx >> 6, k = idx & 63;
        w4s[k*W4S+oc] = g_weff4[b][oc][k];
    }
    if (t < CC) scas[t] = g_sca[b][t];
    __syncthreads();

    for (int idx = t; idx < CC*TP4; idx += 256) {
        int c = idx >> 6, pix = idx & 63;
        bufA[c*S4+pix] = g_t[b][c][pixbase+pix] * scas[c];
    }
    __syncthreads();

    int g4 = t >> 4, p16 = t & 15;
    int p0 = p16 * 4;

    // conv3 (64->64): 2 oc-pairs x 4 pix per thread, then y -> bufB
    {
        int oc0 = g4 * 4;
        u64 acc[2][4];
        #pragma unroll
        for (int o = 0; o < 2; o++)
            #pragma unroll
            for (int p = 0; p < 4; p++) acc[o][p] = 0ULL;
        #pragma unroll 4
        for (int k = 0; k < CC; k++) {
            float4 xv = *(const float4*)(bufA + k*S4 + p0);
            u64 xp[4];
            PACK2(xp[0], xv.x); PACK2(xp[1], xv.y); PACK2(xp[2], xv.z); PACK2(xp[3], xv.w);
            ulonglong2 wv = *(const ulonglong2*)(w3s + k*S4 + oc0);
            #pragma unroll
            for (int p = 0; p < 4; p++) {
                FMA2(acc[0][p], wv.x, xp[p]);
                FMA2(acc[1][p], wv.y, xp[p]);
            }
        }
        #pragma unroll
        for (int op = 0; op < 2; op++) {
            int ocA = oc0 + 2*op, ocB = ocA + 1;
            const float* IA = inp + ((size_t)(b*CC+ocA))*HWP + pixbase + p0;
            const float* IB = inp + ((size_t)(b*CC+ocB))*HWP + pixbase + p0;
            float4 ivA = *(const float4*)IA;
            float4 ivB = *(const float4*)IB;
            float bA = b3[ocA], bB = b3[ocB], btA = beta[ocA], btB = beta[ocB];
            float iA[4] = {ivA.x,ivA.y,ivA.z,ivA.w};
            float iB[4] = {ivB.x,ivB.y,ivB.z,ivB.w};
            #pragma unroll
            for (int p = 0; p < 4; p++) {
                float a, c; UNPACK2(a, c, acc[op][p]);
                bufB[ocA*S4+p0+p] = iA[p] + (a+bA)*btA;
                bufB[ocB*S4+p0+p] = iB[p] + (c+bB)*btB;
            }
        }
    }
    __syncthreads();

    // LN2 stats over y
    {
        int p = t >> 2, q = t & 3;
        float s = 0.f, sq = 0.f;
        #pragma unroll
        for (int c = 0; c < 16; c++) {
            float v = bufB[(q*16+c)*S4 + p];
            s += v; sq += v*v;
        }
        redS[q*TP4+p] = s; redQ[q*TP4+p] = sq;
    }
    __syncthreads();
    if (t < TP4) {
        float s  = redS[t]+redS[TP4+t]+redS[2*TP4+t]+redS[3*TP4+t];
        float sq = redQ[t]+redQ[TP4+t]+redQ[2*TP4+t]+redQ[3*TP4+t];
        float m = s * (1.f/CC);
        float var = sq * (1.f/CC) - m*m;
        mu[t] = m; rstd[t] = rsqrtf(var + EPSF);
    }
    __syncthreads();
    for (int idx = t; idx < CC*TP4; idx += 256) {
        int c = idx >> 6, pix = idx & 63;
        bufA[c*S4+pix] = (bufB[c*S4+pix]-mu[pix])*rstd[pix]*ln2w[c] + ln2b[c];
    }
    __syncthreads();

    // conv4 (64->128): 4 oc-pairs x 4 pix per thread
    u64 acc4[4][4];
    int oc4 = g4 * 8;
    #pragma unroll
    for (int o = 0; o < 4; o++)
        #pragma unroll
        for (int p = 0; p < 4; p++) acc4[o][p] = 0ULL;
    #pragma unroll 4
    for (int k = 0; k < CC; k++) {
        float4 xv = *(const float4*)(bufA + k*S4 + p0);
        u64 xp[4];
        PACK2(xp[0], xv.x); PACK2(xp[1], xv.y); PACK2(xp[2], xv.z); PACK2(xp[3], xv.w);
        const ulonglong2* wr = (const ulonglong2*)(w4s + k*W4S + oc4);
        ulonglong2 wA = wr[0], wB = wr[1];
        u64 wp[4] = {wA.x, wA.y, wB.x, wB.y};
        #pragma unroll
        for (int o = 0; o < 4; o++)
            #pragma unroll
            for (int p = 0; p < 4; p++)
                FMA2(acc4[o][p], wp[o], xp[p]);
    }
    __syncthreads();
    // SimpleGate: upper half to bufA, then lower half multiplies
    if (oc4 >= CC) {
        #pragma unroll
        for (int op = 0; op < 4; op++) {
            int ocA = oc4 + 2*op - CC, ocB = ocA + 1;
            float bA = b4[oc4+2*op], bB = b4[oc4+2*op+1];
            #pragma unroll
            for (int p = 0; p < 4; p++) {
                float a, c; UNPACK2(a, c, acc4[op][p]);
                bufA[ocA*S4+p0+p] = a + bA;
                bufA[ocB*S4+p0+p] = c + bB;
            }
        }
    }
    __syncthreads();
    if (oc4 < CC) {
        #pragma unroll
        for (int op = 0; op < 4; op++) {
            int ocA = oc4 + 2*op, ocB = ocA + 1;
            float bA = b4[ocA], bB = b4[ocB];
            #pragma unroll
            for (int p = 0; p < 4; p++) {
                float a, c; UNPACK2(a, c, acc4[op][p]);
                bufA[ocA*S4+p0+p] = (a + bA) * bufA[ocA*S4+p0+p];
                bufA[ocB*S4+p0+p] = (c + bB) * bufA[ocB*S4+p0+p];
            }
        }
    }
    __syncthreads();

    // conv5 (64->64) + final residual
    {
        int oc0 = g4 * 4;
        u64 acc[2][4];
        #pragma unroll
        for (int o = 0; o < 2; o++)
            #pragma unroll
            for (int p = 0; p < 4; p++) acc[o][p] = 0ULL;
        #pragma unroll 4
        for (int k = 0; k < CC; k++) {
            float4 xv = *(const float4*)(bufA + k*S4 + p0);
            u64 xp[4];
            PACK2(xp[0], xv.x); PACK2(xp[1], xv.y); PACK2(xp[2], xv.z); PACK2(xp[3], xv.w);
            ulonglong2 wv = *(const ulonglong2*)(w5s + k*S4 + oc0);
            #pragma unroll
            for (int p = 0; p < 4; p++) {
                FMA2(acc[0][p], wv.x, xp[p]);
                FMA2(acc[1][p], wv.y, xp[p]);
            }
        }
        #pragma unroll
        for (int op = 0; op < 2; op++) {
            int ocA = oc0 + 2*op, ocB = ocA + 1;
            float bA = b5[ocA], bB = b5[ocB], gA = gamma[ocA], gB = gamma[ocB];
            float* OA = out + ((size_t)(b*CC+ocA))*HWP + pixbase + p0;
            float* OB = out + ((size_t)(b*CC+ocB))*HWP + pixbase + p0;
            float4 oA, oB;
            float a, c;
            UNPACK2(a, c, acc[op][0]);
            oA.x = bufB[ocA*S4+p0+0] + (a+bA)*gA; oB.x = bufB[ocB*S4+p0+0] + (c+bB)*gB;
            UNPACK2(a, c, acc[op][1]);
            oA.y = bufB[ocA*S4+p0+1] + (a+bA)*gA; oB.y = bufB[ocB*S4+p0+1] + (c+bB)*gB;
            UNPACK2(a, c, acc[op][2]);
            oA.z = bufB[ocA*S4+p0+2] + (a+bA)*gA; oB.z = bufB[ocB*S4+p0+2] + (c+bB)*gB;
            UNPACK2(a, c, acc[op][3]);
            oA.w = bufB[ocA*S4+p0+3] + (a+bA)*gA; oB.w = bufB[ocB*S4+p0+3] + (c+bB)*gB;
            *(float4*)OA = oA;
            *(float4*)OB = oB;
        }
    }
}

// ---------------- launch ----------------
extern "C" void kernel_launch(void* const* d_in, const int* in_sizes, int n_in,
                              void* d_out, int out_size)
{
    const float* inp   = (const float*)d_in[0];
    const float* probs = (const float*)d_in[1];
    const float* ln1w  = (const float*)d_in[2];
    const float* ln1b  = (const float*)d_in[3];
    const float* ln2w  = (const float*)d_in[4];
    const float* ln2b  = (const float*)d_in[5];
    const float* w1    = (const float*)d_in[6];
    const float* b1    = (const float*)d_in[7];
    const float* la1   = (const float*)d_in[8];
    const float* lb1   = (const float*)d_in[9];
    const float* w2    = (const float*)d_in[10];
    const float* b2    = (const float*)d_in[11];
    const float* la2   = (const float*)d_in[12];
    const float* lb2   = (const float*)d_in[13];
    const float* wsca  = (const float*)d_in[14];
    const float* bsca  = (const float*)d_in[15];
    const float* la_s  = (const float*)d_in[16];
    const float* lb_s  = (const float*)d_in[17];
    const float* w3    = (const float*)d_in[18];
    const float* b3    = (const float*)d_in[19];
    const float* la3   = (const float*)d_in[20];
    const float* lb3   = (const float*)d_in[21];
    const float* w4    = (const float*)d_in[22];
    const float* b4    = (const float*)d_in[23];
    const float* la4   = (const float*)d_in[24];
    const float* lb4   = (const float*)d_in[25];
    const float* w5    = (const float*)d_in[26];
    const float* b5    = (const float*)d_in[27];
    const float* la5   = (const float*)d_in[28];
    const float* lb5   = (const float*)d_in[29];
    const float* beta  = (const float*)d_in[30];
    const float* gamma = (const float*)d_in[31];
    float* out = (float*)d_out;

    const int smem1 = (64*XS1 + 64*WS1 + 2*TP1 + 2*TP1 + TP1 + TP1) * (int)sizeof(float);
    const int smem4 = (CC*S4*4 + CC*W4S + TP4*2 + 4*TP4*2 + CC) * (int)sizeof(float);
    cudaFuncSetAttribute(k1_ln_conv1, cudaFuncAttributeMaxDynamicSharedMemorySize, smem1);
    cudaFuncSetAttribute(k4_final,    cudaFuncAttributeMaxDynamicSharedMemorySize, smem4);

    k0_weights<<<BB, 256>>>(probs, w1, la1, lb1, w2, la2, lb2,
                            wsca, la_s, lb_s, w3, la3, lb3,
                            w4, la4, lb4, w5, la5, lb5);
    k1_ln_conv1<<<dim3(HWP/TP1, BB), 256, smem1>>>(inp, ln1w, ln1b, b1);
    k2_dw_gate_pool<<<dim3(HH/8, CC, BB), 256>>>(b2);
    k3_sca<<<BB, CC>>>(bsca);
    k4_final<<<dim3(HWP/TP4, BB), 256, smem4>>>(inp, ln2w, ln2b, b3, b4, b5,
                                                beta, gamma, out);
}